// round 6
// baseline (speedup 1.0000x reference)
#include <cuda_runtime.h>
#include <cstdint>
#include <cfloat>
#include <math.h>

#define Bb 32
#define Nn 64
#define Mm 64
#define Cc 64
#define C1d 16
#define Hh 256
#define TH 768
#define FD 912
#define GD 2992

// ---------------- device scratch (no allocations allowed) ----------------
__device__ float g_F[(size_t)Bb * Nn * FD];     // f [2048][912]
__device__ float g_XW1[(size_t)Bb * Nn * TH];   // gru1d input proj [2048][768]
__device__ float g_WihT2[Cc * TH];
__device__ float g_WhhT2[Hh * TH];
__device__ float g_Whh1T[Hh * TH];
__device__ float g_fc1Wt[GD * Hh];
__device__ float g_G[Bb * GD];
__device__ float g_H2[Bb * Hh];
__device__ int   g_perm1[Nn * Mm];
__device__ int   g_perm2[Nn * Nn];

// ---------------- helpers ----------------
__device__ __forceinline__ unsigned long long pack2(float lo, float hi) {
    unsigned long long r;
    asm("mov.b64 %0, {%1, %2};" : "=l"(r) : "f"(lo), "f"(hi));
    return r;
}
__device__ __forceinline__ float2 unpack2(unsigned long long v) {
    float2 r;
    asm("mov.b64 {%0, %1}, %2;" : "=f"(r.x), "=f"(r.y) : "l"(v));
    return r;
}
__device__ __forceinline__ void ffma2(unsigned long long& d, unsigned long long a, unsigned long long b) {
    asm("fma.rn.f32x2 %0, %1, %2, %0;" : "+l"(d) : "l"(a), "l"(b));
}
__device__ __forceinline__ float sigmoidf_(float x) { return 1.0f / (1.0f + __expf(-x)); }

// ---------------- perm canonicalization: detect int64 vs int32 ----------------
__global__ void conv_perm_kernel(const int* __restrict__ raw, int* __restrict__ out, int n) {
    __shared__ int notI64;
    if (threadIdx.x == 0) notI64 = 0;
    __syncthreads();
    for (int i = threadIdx.x; i < n / 2; i += blockDim.x)
        if (raw[2 * i + 1] != 0) notI64 = 1;
    __syncthreads();
    if (notI64) { for (int i = threadIdx.x; i < n; i += blockDim.x) out[i] = raw[i]; }
    else        { for (int i = threadIdx.x; i < n; i += blockDim.x) out[i] = raw[2 * i]; }
}

// ---------------- transpose in[R][C] -> out[C][R] ----------------
__global__ void transpose_kernel(const float* __restrict__ in, float* __restrict__ out, int R, int C) {
    int idx = blockIdx.x * 256 + threadIdx.x;
    if (idx < R * C) { int r = idx / C, c = idx % C; out[c * R + r] = in[idx]; }
}

// ---------------- stats over states + x1 copy -> F[:, 0:400] ----------------
__global__ void stats_kernel(const float* __restrict__ states, const float* __restrict__ x1) {
    int bi = blockIdx.x;               // b*64 + i
    int b = bi >> 6, i = bi & 63;
    int c = threadIdx.x;               // 64 threads
    float* fr = g_F + (size_t)bi * FD;

    float mx = -FLT_MAX, mn = FLT_MAX, sm = 0.0f;
    for (int n = 0; n < Nn; ++n) {     // reduce axis 1 (n), m = i
        float v = states[(((size_t)(b * Nn + n)) * Mm + i) * Cc + c];
        mx = fmaxf(mx, v); mn = fminf(mn, v); sm += v;
    }
    fr[C1d + c]          = mx;
    fr[C1d + Cc + c]     = sm * (1.0f / 64.0f);
    fr[C1d + 2 * Cc + c] = mn;

    mx = -FLT_MAX; mn = FLT_MAX; sm = 0.0f;
    for (int m = 0; m < Mm; ++m) {     // reduce axis 2 (m), n = i
        float v = states[(((size_t)(b * Nn + i)) * Mm + m) * Cc + c];
        mx = fmaxf(mx, v); mn = fminf(mn, v); sm += v;
    }
    fr[C1d + 3 * Cc + c] = mx;
    fr[C1d + 4 * Cc + c] = sm * (1.0f / 64.0f);
    fr[C1d + 5 * Cc + c] = mn;

    if (c < C1d) fr[c] = x1[bi * C1d + c];
}

// ---------------- persistent 2D GRU, fused input proj, fp32x2 ----------------
// grid (128,2), block 256. 16 sequences per CTA as 8 lane-pairs.
__global__ void __launch_bounds__(256, 2)
gru2d_kernel(const float* __restrict__ states,
             const float* __restrict__ bih, const float* __restrict__ bhh) {
    const int dir  = blockIdx.y;
    const int seq0 = blockIdx.x * 16;
    const int j    = threadIdx.x;

    __shared__ __align__(16) float sh_h[256][18];  // [k][g], pairs contiguous
    __shared__ __align__(16) float sh_x[64][18];
    __shared__ int sh_row[16];

    #pragma unroll
    for (int g = 0; g < 18; ++g) sh_h[j][g] = 0.0f;

    const float bihr = bih[j],      bihz = bih[Hh + j],      bihn = bih[2 * Hh + j];
    const float bhhr = bhh[j],      bhhz = bhh[Hh + j],      bhhn = bhh[2 * Hh + j];
    __syncthreads();

    for (int t = 0; t < 64; ++t) {
        if (j < 16) {
            int seq = seq0 + j;
            int b = seq >> 6, n = seq & 63;
            sh_row[j] = (dir == 0)
                ? (b * Nn + n) * Mm + g_perm1[n * Mm + t]
                : (b * Nn + g_perm2[n * Nn + t]) * Mm + n;
        }
        __syncthreads();
        for (int idx = j; idx < 16 * 64; idx += 256) {
            int g = idx >> 6, c = idx & 63;
            sh_x[c][g] = states[(size_t)sh_row[g] * Cc + c];
        }
        __syncthreads();

        unsigned long long accR[8], accZ[8], giN[8], ghN[8];
        #pragma unroll
        for (int g = 0; g < 8; ++g) {
            accR[g] = pack2(bihr + bhhr, bihr + bhhr);
            accZ[g] = pack2(bihz + bhhz, bihz + bhhz);
            giN[g]  = pack2(bihn, bihn);
            ghN[g]  = pack2(bhhn, bhhn);
        }

        const float* wpx = g_WihT2 + j;
        #pragma unroll 4
        for (int k = 0; k < Cc; ++k) {
            float wr = wpx[k * TH], wz = wpx[k * TH + Hh], wn = wpx[k * TH + 2 * Hh];
            unsigned long long wr2 = pack2(wr, wr), wz2 = pack2(wz, wz), wn2 = pack2(wn, wn);
            #pragma unroll
            for (int g = 0; g < 8; ++g) {
                unsigned long long xv = *reinterpret_cast<const unsigned long long*>(&sh_x[k][2 * g]);
                ffma2(accR[g], wr2, xv);
                ffma2(accZ[g], wz2, xv);
                ffma2(giN[g],  wn2, xv);
            }
        }
        const float* wph = g_WhhT2 + j;
        #pragma unroll 4
        for (int k = 0; k < Hh; ++k) {
            float wr = wph[k * TH], wz = wph[k * TH + Hh], wn = wph[k * TH + 2 * Hh];
            unsigned long long wr2 = pack2(wr, wr), wz2 = pack2(wz, wz), wn2 = pack2(wn, wn);
            #pragma unroll
            for (int g = 0; g < 8; ++g) {
                unsigned long long hv = *reinterpret_cast<const unsigned long long*>(&sh_h[k][2 * g]);
                ffma2(accR[g], wr2, hv);
                ffma2(accZ[g], wz2, hv);
                ffma2(ghN[g],  wn2, hv);
            }
        }

        float hnew[16];
        #pragma unroll
        for (int gg = 0; gg < 8; ++gg) {
            float2 aR = unpack2(accR[gg]);
            float2 aZ = unpack2(accZ[gg]);
            float2 gN = unpack2(giN[gg]);
            float2 hN = unpack2(ghN[gg]);
            float r0 = sigmoidf_(aR.x), z0 = sigmoidf_(aZ.x);
            float n0 = tanhf(gN.x + r0 * hN.x);
            hnew[2 * gg]     = (1.0f - z0) * n0 + z0 * sh_h[j][2 * gg];
            float r1 = sigmoidf_(aR.y), z1 = sigmoidf_(aZ.y);
            float n1 = tanhf(gN.y + r1 * hN.y);
            hnew[2 * gg + 1] = (1.0f - z1) * n1 + z1 * sh_h[j][2 * gg + 1];
        }
        __syncthreads();
        #pragma unroll
        for (int g = 0; g < 16; ++g) sh_h[j][g] = hnew[g];
        __syncthreads();
    }

    const int off = (dir == 0) ? (C1d + 6 * Cc) : (C1d + 6 * Cc + Hh);  // 400 / 656
    #pragma unroll
    for (int g = 0; g < 16; ++g)
        g_F[(size_t)(seq0 + g) * FD + off + j] = sh_h[j][g];
}

// ---------------- SGEMM: C[M][N] = A[M][K] @ B[N][K]^T + bias[N] ----------------
// grid (N/64, M/64), block (16,16). K % 16 == 0.
__global__ void gemm64_kernel(const float* __restrict__ A, const float* __restrict__ Bm,
                              const float* __restrict__ bias, float* __restrict__ Cm,
                              int K, int Ndim) {
    __shared__ __align__(16) float As[16][68];
    __shared__ __align__(16) float Bs[16][68];
    const int tx = threadIdx.x, ty = threadIdx.y;
    const int tid = ty * 16 + tx;
    const int m0 = blockIdx.y * 64, n0 = blockIdx.x * 64;

    float acc[4][4];
    #pragma unroll
    for (int i = 0; i < 4; ++i)
        #pragma unroll
        for (int jj = 0; jj < 4; ++jj) acc[i][jj] = 0.0f;

    for (int k0 = 0; k0 < K; k0 += 16) {
        for (int e = tid; e < 1024; e += 256) {
            int r = e >> 4, kk = e & 15;
            As[kk][r] = A[(size_t)(m0 + r) * K + k0 + kk];
            Bs[kk][r] = Bm[(size_t)(n0 + r) * K + k0 + kk];
        }
        __syncthreads();
        #pragma unroll
        for (int kk = 0; kk < 16; ++kk) {
            float4 a4 = *reinterpret_cast<const float4*>(&As[kk][ty * 4]);
            float4 b4 = *reinterpret_cast<const float4*>(&Bs[kk][tx * 4]);
            float av[4] = {a4.x, a4.y, a4.z, a4.w};
            float bv[4] = {b4.x, b4.y, b4.z, b4.w};
            #pragma unroll
            for (int i = 0; i < 4; ++i)
                #pragma unroll
                for (int jj = 0; jj < 4; ++jj)
                    acc[i][jj] = fmaf(av[i], bv[jj], acc[i][jj]);
        }
        __syncthreads();
    }
    #pragma unroll
    for (int i = 0; i < 4; ++i)
        #pragma unroll
        for (int jj = 0; jj < 4; ++jj)
            Cm[(size_t)(m0 + ty * 4 + i) * Ndim + n0 + tx * 4 + jj] =
                acc[i][jj] + bias[n0 + tx * 4 + jj];
}

// ---------------- 1D GRU: one persistent block per batch, all 64 steps ----------------
__global__ void gru1d_kernel(const float* __restrict__ bhh) {
    const int b = blockIdx.x;
    const int j = threadIdx.x;      // 0..255
    __shared__ float sh[Hh];
    sh[j] = 0.0f;
    const float br = bhh[j], bz = bhh[Hh + j], bn = bhh[2 * Hh + j];
    __syncthreads();

    for (int t = 0; t < 64; ++t) {
        float aR = br, aZ = bz, aN = bn;
        const float* wp = g_Whh1T + j;
        #pragma unroll 4
        for (int k = 0; k < Hh; ++k) {
            float hv = sh[k];
            aR = fmaf(wp[k * TH],          hv, aR);
            aZ = fmaf(wp[k * TH + Hh],     hv, aZ);
            aN = fmaf(wp[k * TH + 2 * Hh], hv, aN);
        }
        const float* xw = g_XW1 + (size_t)(b * 64 + t) * TH;  // includes bih
        float r = sigmoidf_(xw[j] + aR);
        float z = sigmoidf_(xw[Hh + j] + aZ);
        float n = tanhf(xw[2 * Hh + j] + r * aN);
        float hnew = (1.0f - z) * n + z * sh[j];
        __syncthreads();
        sh[j] = hnew;
        __syncthreads();
    }
    g_G[(size_t)b * GD + 3 * FD + j] = sh[j];   // hlast -> g[:, 2736:2992]
}

// ---------------- g = [f.max(1), f.mean(1), f.min(1)] -> G[:, 0:2736] ----------------
__global__ void finalg_kernel() {
    const int b = blockIdx.x;
    for (int c = threadIdx.x; c < FD; c += 256) {
        float mx = -FLT_MAX, mn = FLT_MAX, sm = 0.0f;
        for (int n = 0; n < Nn; ++n) {
            float v = g_F[(size_t)(b * Nn + n) * FD + c];
            mx = fmaxf(mx, v); mn = fminf(mn, v); sm += v;
        }
        g_G[(size_t)b * GD + c]          = mx;
        g_G[(size_t)b * GD + FD + c]     = sm * (1.0f / 64.0f);
        g_G[(size_t)b * GD + 2 * FD + c] = mn;
    }
}

// ---------------- fc1 (relu) ----------------
__global__ void fc1_kernel(const float* __restrict__ fc1_b) {
    const int b = blockIdx.x;
    const int o = threadIdx.x;      // 0..255
    __shared__ float sg[GD];
    for (int k = o; k < GD; k += 256) sg[k] = g_G[(size_t)b * GD + k];
    __syncthreads();
    float acc = fc1_b[o];
    #pragma unroll 4
    for (int k = 0; k < GD; ++k) acc = fmaf(sg[k], g_fc1Wt[(size_t)k * Hh + o], acc);
    g_H2[b * Hh + o] = fmaxf(acc, 0.0f);
}

// ---------------- fc2 ----------------
__global__ void fc2_kernel(const float* __restrict__ fc2_W, const float* __restrict__ fc2_b,
                           float* __restrict__ out) {
    const int b = blockIdx.x;
    const int j = threadIdx.x;
    __shared__ float red[256];
    red[j] = g_H2[b * Hh + j] * fc2_W[j];
    __syncthreads();
    for (int s = 128; s > 0; s >>= 1) {
        if (j < s) red[j] += red[j + s];
        __syncthreads();
    }
    if (j == 0) out[b] = red[0] + fc2_b[0];
}

// ---------------- launch ----------------
extern "C" void kernel_launch(void* const* d_in, const int* in_sizes, int n_in,
                              void* d_out, int out_size) {
    const float* x1     = (const float*)d_in[0];
    const float* states = (const float*)d_in[1];
    const int*   perm1r = (const int*)d_in[2];
    const int*   perm2r = (const int*)d_in[3];
    const float* g2Wih  = (const float*)d_in[4];
    const float* g2Whh  = (const float*)d_in[5];
    const float* g2bih  = (const float*)d_in[6];
    const float* g2bhh  = (const float*)d_in[7];
    const float* g1Wih  = (const float*)d_in[8];
    const float* g1Whh  = (const float*)d_in[9];
    const float* g1bih  = (const float*)d_in[10];
    const float* g1bhh  = (const float*)d_in[11];
    const float* fc1W   = (const float*)d_in[12];
    const float* fc1b   = (const float*)d_in[13];
    const float* fc2W   = (const float*)d_in[14];
    const float* fc2b   = (const float*)d_in[15];
    float* out = (float*)d_out;

    int *p1, *p2;
    float *wihT2, *whhT2, *whh1T, *fc1Wt, *xw1, *Fbuf;
    cudaGetSymbolAddress((void**)&p1,    g_perm1);
    cudaGetSymbolAddress((void**)&p2,    g_perm2);
    cudaGetSymbolAddress((void**)&wihT2, g_WihT2);
    cudaGetSymbolAddress((void**)&whhT2, g_WhhT2);
    cudaGetSymbolAddress((void**)&whh1T, g_Whh1T);
    cudaGetSymbolAddress((void**)&fc1Wt, g_fc1Wt);
    cudaGetSymbolAddress((void**)&xw1,   g_XW1);
    cudaGetSymbolAddress((void**)&Fbuf,  g_F);

    conv_perm_kernel<<<1, 256>>>(perm1r, p1, Nn * Mm);
    conv_perm_kernel<<<1, 256>>>(perm2r, p2, Nn * Nn);

    transpose_kernel<<<(TH * Cc + 255) / 256, 256>>>(g2Wih, wihT2, TH, Cc);
    transpose_kernel<<<(TH * Hh + 255) / 256, 256>>>(g2Whh, whhT2, TH, Hh);
    transpose_kernel<<<(TH * Hh + 255) / 256, 256>>>(g1Whh, whh1T, TH, Hh);
    transpose_kernel<<<(Hh * GD + 255) / 256, 256>>>(fc1W, fc1Wt, Hh, GD);

    stats_kernel<<<Bb * Nn, 64>>>(states, x1);

    dim3 ggrid(128, 2);
    gru2d_kernel<<<ggrid, 256>>>(states, g2bih, g2bhh);

    // XW1 = F @ g1Wih^T + g1bih   (M=2048, N=768, K=912)
    dim3 gemmg(TH / 64, (Bb * Nn) / 64);
    gemm64_kernel<<<gemmg, dim3(16, 16)>>>(Fbuf, g1Wih, g1bih, xw1, FD, TH);

    gru1d_kernel<<<Bb, Hh>>>(g1bhh);
    finalg_kernel<<<Bb, 256>>>();
    fc1_kernel<<<Bb, Hh>>>(fc1b);
    fc2_kernel<<<Bb, 256>>>(fc2W, fc2b, out);
}

// round 7
// speedup vs baseline: 1.5523x; 1.5523x over previous
#include <cuda_runtime.h>
#include <cstdint>
#include <cfloat>
#include <math.h>

#define Bb 32
#define Nn 64
#define Mm 64
#define Cc 64
#define C1d 16
#define Hh 256
#define TH 768
#define FD 912
#define GD 2992

// ---------------- device scratch (no allocations allowed) ----------------
__device__ float g_P[(size_t)Bb * Nn * Mm * TH];   // input proj of every states row [131072][768]
__device__ float g_F[(size_t)Bb * Nn * FD];        // f [2048][912]
__device__ float g_XW1[(size_t)Bb * Nn * TH];      // gru1d input proj [2048][768]
__device__ float g_WhhT2[Hh * TH];                 // [256][768]
__device__ float g_Whh1T[Hh * TH];                 // [256][768]
__device__ float g_fc1Wt[GD * Hh];                 // [2992][256]
__device__ float g_G[Bb * GD];
__device__ float g_H2[Bb * Hh];
__device__ int   g_perm1[Nn * Mm];
__device__ int   g_perm2[Nn * Nn];

// ---------------- helpers ----------------
__device__ __forceinline__ unsigned long long pack2(float lo, float hi) {
    unsigned long long r;
    asm("mov.b64 %0, {%1, %2};" : "=l"(r) : "f"(lo), "f"(hi));
    return r;
}
__device__ __forceinline__ float2 unpack2(unsigned long long v) {
    float2 r;
    asm("mov.b64 {%0, %1}, %2;" : "=f"(r.x), "=f"(r.y) : "l"(v));
    return r;
}
__device__ __forceinline__ void ffma2(unsigned long long& d, unsigned long long a, unsigned long long b) {
    asm("fma.rn.f32x2 %0, %1, %2, %0;" : "+l"(d) : "l"(a), "l"(b));
}
__device__ __forceinline__ float sigmoidf_(float x) { return 1.0f / (1.0f + __expf(-x)); }

__device__ __forceinline__ void cp_async16(uint32_t dst, const void* src) {
    asm volatile("cp.async.cg.shared.global [%0], [%1], 16;" :: "r"(dst), "l"(src));
}

// ---------------- perm canonicalization: detect int64 vs int32 ----------------
__global__ void conv_perm_kernel(const int* __restrict__ raw, int* __restrict__ out, int n) {
    __shared__ int notI64;
    if (threadIdx.x == 0) notI64 = 0;
    __syncthreads();
    for (int i = threadIdx.x; i < n / 2; i += blockDim.x)
        if (raw[2 * i + 1] != 0) notI64 = 1;
    __syncthreads();
    if (notI64) { for (int i = threadIdx.x; i < n; i += blockDim.x) out[i] = raw[i]; }
    else        { for (int i = threadIdx.x; i < n; i += blockDim.x) out[i] = raw[2 * i]; }
}

// ---------------- transpose in[R][C] -> out[C][R] ----------------
__global__ void transpose_kernel(const float* __restrict__ in, float* __restrict__ out, int R, int C) {
    int idx = blockIdx.x * 256 + threadIdx.x;
    if (idx < R * C) { int r = idx / C, c = idx % C; out[c * R + r] = in[idx]; }
}

// ---------------- stats over states + x1 copy -> F[:, 0:400] ----------------
__global__ void stats_kernel(const float* __restrict__ states, const float* __restrict__ x1) {
    int bi = blockIdx.x;               // b*64 + i
    int b = bi >> 6, i = bi & 63;
    int c = threadIdx.x;               // 64 threads
    float* fr = g_F + (size_t)bi * FD;

    float mx = -FLT_MAX, mn = FLT_MAX, sm = 0.0f;
    for (int n = 0; n < Nn; ++n) {     // reduce axis 1 (n), m = i
        float v = states[(((size_t)(b * Nn + n)) * Mm + i) * Cc + c];
        mx = fmaxf(mx, v); mn = fminf(mn, v); sm += v;
    }
    fr[C1d + c]          = mx;
    fr[C1d + Cc + c]     = sm * (1.0f / 64.0f);
    fr[C1d + 2 * Cc + c] = mn;

    mx = -FLT_MAX; mn = FLT_MAX; sm = 0.0f;
    for (int m = 0; m < Mm; ++m) {     // reduce axis 2 (m), n = i
        float v = states[(((size_t)(b * Nn + i)) * Mm + m) * Cc + c];
        mx = fmaxf(mx, v); mn = fminf(mn, v); sm += v;
    }
    fr[C1d + 3 * Cc + c] = mx;
    fr[C1d + 4 * Cc + c] = sm * (1.0f / 64.0f);
    fr[C1d + 5 * Cc + c] = mn;

    if (c < C1d) fr[c] = x1[bi * C1d + c];
}

// ---------------- SGEMM: C[M][N] = A[M][K] @ B[N][K]^T + bias[N] ----------------
// grid (N/64, M/64), block (16,16). K % 16 == 0.
__global__ void gemm64_kernel(const float* __restrict__ A, const float* __restrict__ Bm,
                              const float* __restrict__ bias, float* __restrict__ Cm,
                              int K, int Ndim) {
    __shared__ __align__(16) float As[16][68];
    __shared__ __align__(16) float Bs[16][68];
    const int tx = threadIdx.x, ty = threadIdx.y;
    const int tid = ty * 16 + tx;
    const int m0 = blockIdx.y * 64, n0 = blockIdx.x * 64;

    float acc[4][4];
    #pragma unroll
    for (int i = 0; i < 4; ++i)
        #pragma unroll
        for (int jj = 0; jj < 4; ++jj) acc[i][jj] = 0.0f;

    for (int k0 = 0; k0 < K; k0 += 16) {
        for (int e = tid; e < 1024; e += 256) {
            int r = e >> 4, kk = e & 15;
            As[kk][r] = A[(size_t)(m0 + r) * K + k0 + kk];
            Bs[kk][r] = Bm[(size_t)(n0 + r) * K + k0 + kk];
        }
        __syncthreads();
        #pragma unroll
        for (int kk = 0; kk < 16; ++kk) {
            float4 a4 = *reinterpret_cast<const float4*>(&As[kk][ty * 4]);
            float4 b4 = *reinterpret_cast<const float4*>(&Bs[kk][tx * 4]);
            float av[4] = {a4.x, a4.y, a4.z, a4.w};
            float bv[4] = {b4.x, b4.y, b4.z, b4.w};
            #pragma unroll
            for (int i = 0; i < 4; ++i)
                #pragma unroll
                for (int jj = 0; jj < 4; ++jj)
                    acc[i][jj] = fmaf(av[i], bv[jj], acc[i][jj]);
        }
        __syncthreads();
    }
    #pragma unroll
    for (int i = 0; i < 4; ++i)
        #pragma unroll
        for (int jj = 0; jj < 4; ++jj)
            Cm[(size_t)(m0 + ty * 4 + i) * Ndim + n0 + tx * 4 + jj] =
                acc[i][jj] + bias[n0 + tx * 4 + jj];
}

// ---------------- persistent 2D GRU (recurrent-only, cp.async xw stream) ----------------
// grid (128,2), block 256, dynamic smem 67648B, 2 CTAs/SM.
// 16 sequences per CTA as 8 lane-pairs; input projection precomputed in g_P.
__global__ void __launch_bounds__(256, 2)
gru2d_kernel(const float* __restrict__ bhh) {
    const int dir  = blockIdx.y;
    const int seq0 = blockIdx.x * 16;
    const int j    = threadIdx.x;

    extern __shared__ __align__(16) float dyn[];
    float (*sh_h)[18] = (float (*)[18])dyn;              // [256][18]
    float* sh_xw = dyn + 256 * 18;                       // [16][768]
    int*   sh_row = (int*)(dyn + 256 * 18 + 16 * TH);    // [16]

    #pragma unroll
    for (int g = 0; g < 18; ++g) sh_h[j][g] = 0.0f;

    const float bhhr = bhh[j], bhhz = bhh[Hh + j], bhhn = bhh[2 * Hh + j];
    const unsigned long long bR2 = pack2(bhhr, bhhr);
    const unsigned long long bZ2 = pack2(bhhz, bhhz);
    const unsigned long long bN2 = pack2(bhhn, bhhn);

    const int my_g   = j >> 4;          // row this thread copies
    const int my_c16 = j & 15;          // chunk lane within row
    uint32_t xw_dst_base = (uint32_t)__cvta_generic_to_shared(sh_xw + my_g * TH);
    __syncthreads();

    for (int t = 0; t < 64; ++t) {
        if (j < 16) {
            int seq = seq0 + j;
            int b = seq >> 6, n = seq & 63;
            sh_row[j] = (dir == 0)
                ? (b * Nn + n) * Mm + g_perm1[n * Mm + t]
                : (b * Nn + g_perm2[n * Nn + t]) * Mm + n;
        }
        __syncthreads();

        // async-gather the 16 precomputed xw rows (16 x 768 floats) into smem
        {
            const float* src_row = g_P + (size_t)sh_row[my_g] * TH;
            #pragma unroll
            for (int i = 0; i < 12; ++i) {
                int c16 = my_c16 + 16 * i;          // 0..191 (16B chunks)
                cp_async16(xw_dst_base + c16 * 16, src_row + c16 * 4);
            }
            asm volatile("cp.async.commit_group;");
        }

        // ----- recurrent matvec: only r, z, gh_n have h terms -----
        unsigned long long accR[8], accZ[8], ghN[8];
        #pragma unroll
        for (int g = 0; g < 8; ++g) { accR[g] = bR2; accZ[g] = bZ2; ghN[g] = bN2; }

        const float* wph = g_WhhT2 + j;
        #pragma unroll 4
        for (int k = 0; k < Hh; ++k) {
            float wr = wph[k * TH], wz = wph[k * TH + Hh], wn = wph[k * TH + 2 * Hh];
            unsigned long long wr2 = pack2(wr, wr), wz2 = pack2(wz, wz), wn2 = pack2(wn, wn);
            #pragma unroll
            for (int g = 0; g < 8; ++g) {
                unsigned long long hv = *reinterpret_cast<const unsigned long long*>(&sh_h[k][2 * g]);
                ffma2(accR[g], wr2, hv);
                ffma2(accZ[g], wz2, hv);
                ffma2(ghN[g],  wn2, hv);
            }
        }

        asm volatile("cp.async.wait_group 0;" ::: "memory");
        __syncthreads();

        float hnew[16];
        #pragma unroll
        for (int gg = 0; gg < 8; ++gg) {
            const float* x0 = sh_xw + (2 * gg) * TH + j;
            const float* x1 = sh_xw + (2 * gg + 1) * TH + j;
            float2 aR = unpack2(accR[gg]);
            float2 aZ = unpack2(accZ[gg]);
            float2 hN = unpack2(ghN[gg]);
            float r0 = sigmoidf_(aR.x + x0[0]);
            float z0 = sigmoidf_(aZ.x + x0[Hh]);
            float n0 = tanhf(x0[2 * Hh] + r0 * hN.x);
            hnew[2 * gg]     = (1.0f - z0) * n0 + z0 * sh_h[j][2 * gg];
            float r1 = sigmoidf_(aR.y + x1[0]);
            float z1 = sigmoidf_(aZ.y + x1[Hh]);
            float n1 = tanhf(x1[2 * Hh] + r1 * hN.y);
            hnew[2 * gg + 1] = (1.0f - z1) * n1 + z1 * sh_h[j][2 * gg + 1];
        }
        __syncthreads();
        #pragma unroll
        for (int g = 0; g < 16; ++g) sh_h[j][g] = hnew[g];
        __syncthreads();
    }

    const int off = (dir == 0) ? (C1d + 6 * Cc) : (C1d + 6 * Cc + Hh);  // 400 / 656
    #pragma unroll
    for (int g = 0; g < 16; ++g)
        g_F[(size_t)(seq0 + g) * FD + off + j] = sh_h[j][g];
}

// ---------------- 1D GRU: grid 16 (batch pairs), block 64, float4 weights ----------------
__global__ void gru1d_kernel(const float* __restrict__ bhh) {
    const int b0 = blockIdx.x * 2;
    const int jg = threadIdx.x;          // 0..63, owns j = jg*4 .. jg*4+3
    __shared__ float2 shh[Hh];           // h pairs for (b0, b0+1)
    for (int k = jg; k < Hh; k += 64) shh[k] = make_float2(0.0f, 0.0f);

    unsigned long long bR[4], bZ[4], bN[4];
    #pragma unroll
    for (int i = 0; i < 4; ++i) {
        int jj = jg * 4 + i;
        bR[i] = pack2(bhh[jj], bhh[jj]);
        bZ[i] = pack2(bhh[Hh + jj], bhh[Hh + jj]);
        bN[i] = pack2(bhh[2 * Hh + jj], bhh[2 * Hh + jj]);
    }
    __syncthreads();

    for (int t = 0; t < 64; ++t) {
        unsigned long long aR[4], aZ[4], aN[4];
        #pragma unroll
        for (int i = 0; i < 4; ++i) { aR[i] = bR[i]; aZ[i] = bZ[i]; aN[i] = bN[i]; }

        const float* wbase = g_Whh1T + jg * 4;
        #pragma unroll 4
        for (int k = 0; k < Hh; ++k) {
            float4 wr4 = *reinterpret_cast<const float4*>(wbase + k * TH);
            float4 wz4 = *reinterpret_cast<const float4*>(wbase + k * TH + Hh);
            float4 wn4 = *reinterpret_cast<const float4*>(wbase + k * TH + 2 * Hh);
            unsigned long long hv = *reinterpret_cast<const unsigned long long*>(&shh[k]);
            ffma2(aR[0], pack2(wr4.x, wr4.x), hv);
            ffma2(aR[1], pack2(wr4.y, wr4.y), hv);
            ffma2(aR[2], pack2(wr4.z, wr4.z), hv);
            ffma2(aR[3], pack2(wr4.w, wr4.w), hv);
            ffma2(aZ[0], pack2(wz4.x, wz4.x), hv);
            ffma2(aZ[1], pack2(wz4.y, wz4.y), hv);
            ffma2(aZ[2], pack2(wz4.z, wz4.z), hv);
            ffma2(aZ[3], pack2(wz4.w, wz4.w), hv);
            ffma2(aN[0], pack2(wn4.x, wn4.x), hv);
            ffma2(aN[1], pack2(wn4.y, wn4.y), hv);
            ffma2(aN[2], pack2(wn4.z, wn4.z), hv);
            ffma2(aN[3], pack2(wn4.w, wn4.w), hv);
        }

        const float* xw0 = g_XW1 + (size_t)(b0 * 64 + t) * TH + jg * 4;
        const float* xw1 = g_XW1 + (size_t)((b0 + 1) * 64 + t) * TH + jg * 4;
        float4 x0r = *reinterpret_cast<const float4*>(xw0);
        float4 x0z = *reinterpret_cast<const float4*>(xw0 + Hh);
        float4 x0n = *reinterpret_cast<const float4*>(xw0 + 2 * Hh);
        float4 x1r = *reinterpret_cast<const float4*>(xw1);
        float4 x1z = *reinterpret_cast<const float4*>(xw1 + Hh);
        float4 x1n = *reinterpret_cast<const float4*>(xw1 + 2 * Hh);
        float x0ra[4] = {x0r.x, x0r.y, x0r.z, x0r.w};
        float x0za[4] = {x0z.x, x0z.y, x0z.z, x0z.w};
        float x0na[4] = {x0n.x, x0n.y, x0n.z, x0n.w};
        float x1ra[4] = {x1r.x, x1r.y, x1r.z, x1r.w};
        float x1za[4] = {x1z.x, x1z.y, x1z.z, x1z.w};
        float x1na[4] = {x1n.x, x1n.y, x1n.z, x1n.w};

        float2 hn[4];
        #pragma unroll
        for (int i = 0; i < 4; ++i) {
            float2 vR = unpack2(aR[i]);
            float2 vZ = unpack2(aZ[i]);
            float2 vN = unpack2(aN[i]);
            float2 hold = shh[jg * 4 + i];
            float r0 = sigmoidf_(vR.x + x0ra[i]);
            float z0 = sigmoidf_(vZ.x + x0za[i]);
            float n0 = tanhf(x0na[i] + r0 * vN.x);
            hn[i].x = (1.0f - z0) * n0 + z0 * hold.x;
            float r1 = sigmoidf_(vR.y + x1ra[i]);
            float z1 = sigmoidf_(vZ.y + x1za[i]);
            float n1 = tanhf(x1na[i] + r1 * vN.y);
            hn[i].y = (1.0f - z1) * n1 + z1 * hold.y;
        }
        __syncthreads();
        #pragma unroll
        for (int i = 0; i < 4; ++i) shh[jg * 4 + i] = hn[i];
        __syncthreads();
    }
    #pragma unroll
    for (int i = 0; i < 4; ++i) {
        int jj = jg * 4 + i;
        g_G[(size_t)b0 * GD + 3 * FD + jj]       = shh[jj].x;
        g_G[(size_t)(b0 + 1) * GD + 3 * FD + jj] = shh[jj].y;
    }
}

// ---------------- g = [f.max(1), f.mean(1), f.min(1)] -> G[:, 0:2736] ----------------
__global__ void finalg_kernel() {
    const int b = blockIdx.x;
    for (int c = threadIdx.x; c < FD; c += 256) {
        float mx = -FLT_MAX, mn = FLT_MAX, sm = 0.0f;
        for (int n = 0; n < Nn; ++n) {
            float v = g_F[(size_t)(b * Nn + n) * FD + c];
            mx = fmaxf(mx, v); mn = fminf(mn, v); sm += v;
        }
        g_G[(size_t)b * GD + c]          = mx;
        g_G[(size_t)b * GD + FD + c]     = sm * (1.0f / 64.0f);
        g_G[(size_t)b * GD + 2 * FD + c] = mn;
    }
}

// ---------------- fc1 (relu) ----------------
__global__ void fc1_kernel(const float* __restrict__ fc1_b) {
    const int b = blockIdx.x;
    const int o = threadIdx.x;
    __shared__ float sg[GD];
    for (int k = o; k < GD; k += 256) sg[k] = g_G[(size_t)b * GD + k];
    __syncthreads();
    float acc = fc1_b[o];
    #pragma unroll 4
    for (int k = 0; k < GD; ++k) acc = fmaf(sg[k], g_fc1Wt[(size_t)k * Hh + o], acc);
    g_H2[b * Hh + o] = fmaxf(acc, 0.0f);
}

// ---------------- fc2 ----------------
__global__ void fc2_kernel(const float* __restrict__ fc2_W, const float* __restrict__ fc2_b,
                           float* __restrict__ out) {
    const int b = blockIdx.x;
    const int j = threadIdx.x;
    __shared__ float red[256];
    red[j] = g_H2[b * Hh + j] * fc2_W[j];
    __syncthreads();
    for (int s = 128; s > 0; s >>= 1) {
        if (j < s) red[j] += red[j + s];
        __syncthreads();
    }
    if (j == 0) out[b] = red[0] + fc2_b[0];
}

// ---------------- launch ----------------
extern "C" void kernel_launch(void* const* d_in, const int* in_sizes, int n_in,
                              void* d_out, int out_size) {
    const float* x1     = (const float*)d_in[0];
    const float* states = (const float*)d_in[1];
    const int*   perm1r = (const int*)d_in[2];
    const int*   perm2r = (const int*)d_in[3];
    const float* g2Wih  = (const float*)d_in[4];
    const float* g2Whh  = (const float*)d_in[5];
    const float* g2bih  = (const float*)d_in[6];
    const float* g2bhh  = (const float*)d_in[7];
    const float* g1Wih  = (const float*)d_in[8];
    const float* g1Whh  = (const float*)d_in[9];
    const float* g1bih  = (const float*)d_in[10];
    const float* g1bhh  = (const float*)d_in[11];
    const float* fc1W   = (const float*)d_in[12];
    const float* fc1b   = (const float*)d_in[13];
    const float* fc2W   = (const float*)d_in[14];
    const float* fc2b   = (const float*)d_in[15];
    float* out = (float*)d_out;

    int *p1, *p2;
    float *whhT2, *whh1T, *fc1Wt, *xw1, *Fbuf, *Pbuf;
    cudaGetSymbolAddress((void**)&p1,    g_perm1);
    cudaGetSymbolAddress((void**)&p2,    g_perm2);
    cudaGetSymbolAddress((void**)&whhT2, g_WhhT2);
    cudaGetSymbolAddress((void**)&whh1T, g_Whh1T);
    cudaGetSymbolAddress((void**)&fc1Wt, g_fc1Wt);
    cudaGetSymbolAddress((void**)&xw1,   g_XW1);
    cudaGetSymbolAddress((void**)&Fbuf,  g_F);
    cudaGetSymbolAddress((void**)&Pbuf,  g_P);

    const int GRU2D_SMEM = (256 * 18 + 16 * TH + 16) * 4;   // 67648
    cudaFuncSetAttribute(gru2d_kernel, cudaFuncAttributeMaxDynamicSharedMemorySize, GRU2D_SMEM);

    // launches 1..5
    conv_perm_kernel<<<1, 256>>>(perm1r, p1, Nn * Mm);
    conv_perm_kernel<<<1, 256>>>(perm2r, p2, Nn * Nn);
    transpose_kernel<<<(TH * Hh + 255) / 256, 256>>>(g2Whh, whhT2, TH, Hh);
    // P = states @ g2Wih^T + g2bih   (M=131072, N=768, K=64)
    {
        dim3 g(TH / 64, (Bb * Nn * Mm) / 64);
        gemm64_kernel<<<g, dim3(16, 16)>>>(states, g2Wih, g2bih, Pbuf, Cc, TH);
    }
    stats_kernel<<<Bb * Nn, 64>>>(states, x1);

    // launch 6 — profiled by ncu (-s 5 -c 1)
    dim3 ggrid(128, 2);
    gru2d_kernel<<<ggrid, 256, GRU2D_SMEM>>>(g2bhh);

    // tail
    transpose_kernel<<<(TH * Hh + 255) / 256, 256>>>(g1Whh, whh1T, TH, Hh);
    {
        // XW1 = F @ g1Wih^T + g1bih   (M=2048, N=768, K=912)
        dim3 g(TH / 64, (Bb * Nn) / 64);
        gemm64_kernel<<<g, dim3(16, 16)>>>(Fbuf, g1Wih, g1bih, xw1, FD, TH);
    }
    gru1d_kernel<<<Bb / 2, 64>>>(g1bhh);
    finalg_kernel<<<Bb, 256>>>();
    transpose_kernel<<<(Hh * GD + 255) / 256, 256>>>(fc1W, fc1Wt, Hh, GD);
    fc1_kernel<<<Bb, Hh>>>(fc1b);
    fc2_kernel<<<Bb, 256>>>(fc2W, fc2b, out);
}

// round 8
// speedup vs baseline: 1.6372x; 1.0548x over previous
#include <cuda_runtime.h>
#include <cstdint>
#include <cfloat>
#include <math.h>

#define Bb 32
#define Nn 64
#define Mm 64
#define Cc 64
#define C1d 16
#define Hh 256
#define TH 768
#define FD 912
#define GD 2992

// ---------------- device scratch ----------------
__device__ float g_P[(size_t)Bb * Nn * Mm * TH];   // input proj of every states row [131072][768]
__device__ float g_F[(size_t)Bb * Nn * FD];        // f [2048][912]
__device__ float g_XW1[(size_t)Bb * Nn * TH];      // gru1d input proj [2048][768]
__device__ float g_WhhT2[Hh * TH];                 // [256][768]
__device__ float g_Whh1T[Hh * TH];                 // [256][768]
__device__ float g_fc1Wt[GD * Hh];                 // [2992][256]
__device__ float g_G[Bb * GD];
__device__ float g_H2[Bb * Hh];
__device__ int   g_perm1[Nn * Mm];
__device__ int   g_perm2[Nn * Nn];

// ---------------- helpers ----------------
__device__ __forceinline__ unsigned long long pack2(float lo, float hi) {
    unsigned long long r;
    asm("mov.b64 %0, {%1, %2};" : "=l"(r) : "f"(lo), "f"(hi));
    return r;
}
__device__ __forceinline__ float2 unpack2(unsigned long long v) {
    float2 r;
    asm("mov.b64 {%0, %1}, %2;" : "=f"(r.x), "=f"(r.y) : "l"(v));
    return r;
}
__device__ __forceinline__ void ffma2(unsigned long long& d, unsigned long long a, unsigned long long b) {
    asm("fma.rn.f32x2 %0, %1, %2, %0;" : "+l"(d) : "l"(a), "l"(b));
}
__device__ __forceinline__ float tanh_fast(float x) {
    float y; asm("tanh.approx.f32 %0, %1;" : "=f"(y) : "f"(x)); return y;
}
__device__ __forceinline__ float sig_fast(float x) {
    return fmaf(tanh_fast(x * 0.5f), 0.5f, 0.5f);
}
__device__ __forceinline__ void cp_async16(uint32_t dst, const void* src) {
    asm volatile("cp.async.cg.shared.global [%0], [%1], 16;" :: "r"(dst), "l"(src));
}

// ---------------- both perm conversions in one kernel (int64 vs int32 detect) ----------------
__global__ void conv_perm2_kernel(const int* __restrict__ r1, const int* __restrict__ r2) {
    const int* raw = blockIdx.x ? r2 : r1;
    int* out = blockIdx.x ? g_perm2 : g_perm1;
    const int n = Nn * Mm;   // 4096 both
    __shared__ int notI64;
    if (threadIdx.x == 0) notI64 = 0;
    __syncthreads();
    for (int i = threadIdx.x; i < n / 2; i += blockDim.x)
        if (raw[2 * i + 1] != 0) notI64 = 1;
    __syncthreads();
    if (notI64) { for (int i = threadIdx.x; i < n; i += blockDim.x) out[i] = raw[i]; }
    else        { for (int i = threadIdx.x; i < n; i += blockDim.x) out[i] = raw[2 * i]; }
}

// ---------------- transpose in[R][C] -> out[C][R] ----------------
__global__ void transpose_kernel(const float* __restrict__ in, float* __restrict__ out, int R, int C) {
    int idx = blockIdx.x * 256 + threadIdx.x;
    if (idx < R * C) { int r = idx / C, c = idx % C; out[c * R + r] = in[idx]; }
}

// ---------------- stats over states + x1 copy -> F[:, 0:400] ----------------
__global__ void stats_kernel(const float* __restrict__ states, const float* __restrict__ x1) {
    int bi = blockIdx.x;               // b*64 + i
    int b = bi >> 6, i = bi & 63;
    int c = threadIdx.x;               // 64 threads
    float* fr = g_F + (size_t)bi * FD;

    float mx = -FLT_MAX, mn = FLT_MAX, sm = 0.0f;
    for (int n = 0; n < Nn; ++n) {
        float v = states[(((size_t)(b * Nn + n)) * Mm + i) * Cc + c];
        mx = fmaxf(mx, v); mn = fminf(mn, v); sm += v;
    }
    fr[C1d + c]          = mx;
    fr[C1d + Cc + c]     = sm * (1.0f / 64.0f);
    fr[C1d + 2 * Cc + c] = mn;

    mx = -FLT_MAX; mn = FLT_MAX; sm = 0.0f;
    for (int m = 0; m < Mm; ++m) {
        float v = states[(((size_t)(b * Nn + i)) * Mm + m) * Cc + c];
        mx = fmaxf(mx, v); mn = fminf(mn, v); sm += v;
    }
    fr[C1d + 3 * Cc + c] = mx;
    fr[C1d + 4 * Cc + c] = sm * (1.0f / 64.0f);
    fr[C1d + 5 * Cc + c] = mn;

    if (c < C1d) fr[c] = x1[bi * C1d + c];
}

// ---------------- SGEMM 128x64 tile: C[M][N] = A[M][K] @ B[N][K]^T + bias[N] ----------------
// grid (N/64, M/128), block (16,16), 8x4 per thread. K % 16 == 0.
__global__ void gemm128_kernel(const float* __restrict__ A, const float* __restrict__ Bm,
                               const float* __restrict__ bias, float* __restrict__ Cm,
                               int K, int Ndim) {
    __shared__ __align__(16) float As[16][132];
    __shared__ __align__(16) float Bs[16][68];
    const int tx = threadIdx.x, ty = threadIdx.y;
    const int tid = ty * 16 + tx;
    const int m0 = blockIdx.y * 128, n0 = blockIdx.x * 64;

    float acc[8][4];
    #pragma unroll
    for (int i = 0; i < 8; ++i)
        #pragma unroll
        for (int jj = 0; jj < 4; ++jj) acc[i][jj] = 0.0f;

    for (int k0 = 0; k0 < K; k0 += 16) {
        #pragma unroll
        for (int e = 0; e < 8; ++e) {
            int idx = tid + e * 256;            // 0..2047
            int r = idx >> 4, kk = idx & 15;
            As[kk][r] = A[(size_t)(m0 + r) * K + k0 + kk];
        }
        #pragma unroll
        for (int e = 0; e < 4; ++e) {
            int idx = tid + e * 256;            // 0..1023
            int r = idx >> 4, kk = idx & 15;
            Bs[kk][r] = Bm[(size_t)(n0 + r) * K + k0 + kk];
        }
        __syncthreads();
        #pragma unroll
        for (int kk = 0; kk < 16; ++kk) {
            float4 a0 = *reinterpret_cast<const float4*>(&As[kk][ty * 8]);
            float4 a1 = *reinterpret_cast<const float4*>(&As[kk][ty * 8 + 4]);
            float4 b4 = *reinterpret_cast<const float4*>(&Bs[kk][tx * 4]);
            float av[8] = {a0.x, a0.y, a0.z, a0.w, a1.x, a1.y, a1.z, a1.w};
            float bv[4] = {b4.x, b4.y, b4.z, b4.w};
            #pragma unroll
            for (int i = 0; i < 8; ++i)
                #pragma unroll
                for (int jj = 0; jj < 4; ++jj)
                    acc[i][jj] = fmaf(av[i], bv[jj], acc[i][jj]);
        }
        __syncthreads();
    }
    float4 bia = *reinterpret_cast<const float4*>(&bias[n0 + tx * 4]);
    #pragma unroll
    for (int i = 0; i < 8; ++i) {
        float4 v = make_float4(acc[i][0] + bia.x, acc[i][1] + bia.y,
                               acc[i][2] + bia.z, acc[i][3] + bia.w);
        *reinterpret_cast<float4*>(&Cm[(size_t)(m0 + ty * 8 + i) * Ndim + n0 + tx * 4]) = v;
    }
}

// ---------------- persistent 2D GRU (recurrent-only, cp.async xw stream) ----------------
// grid (128,2), block 256, dyn smem 73728B, 2 CTAs/SM. 16 seqs/CTA as 8 lane-pairs.
__global__ void __launch_bounds__(256, 2)
gru2d_kernel(const float* __restrict__ bhh) {
    const int dir  = blockIdx.y;
    const int seq0 = blockIdx.x * 16;
    const int j    = threadIdx.x;

    extern __shared__ __align__(16) float dyn[];
    float (*sh_h)[20] = (float (*)[20])dyn;              // [256][20] (pad for 16B align)
    float* sh_xw  = dyn + 256 * 20;                      // [16][768]
    int*   sh_row = (int*)(dyn + 256 * 20 + 16 * TH);    // [16][64]

    #pragma unroll
    for (int g = 0; g < 16; ++g) sh_h[j][g] = 0.0f;

    // precompute all gather rows
    for (int e = j; e < 16 * 64; e += 256) {
        int g = e >> 6, t = e & 63;
        int seq = seq0 + g;
        int b = seq >> 6, n = seq & 63;
        sh_row[e] = (dir == 0)
            ? (b * Nn + n) * Mm + g_perm1[n * Mm + t]
            : (b * Nn + g_perm2[n * Nn + t]) * Mm + n;
    }

    const float bhhr = bhh[j], bhhz = bhh[Hh + j], bhhn = bhh[2 * Hh + j];
    const unsigned long long bR2 = pack2(bhhr, bhhr);
    const unsigned long long bZ2 = pack2(bhhz, bhhz);
    const unsigned long long bN2 = pack2(bhhn, bhhn);

    const int my_g   = j >> 4;
    const int my_c16 = j & 15;
    uint32_t xw_dst_base = (uint32_t)__cvta_generic_to_shared(sh_xw + my_g * TH);
    __syncthreads();

    for (int t = 0; t < 64; ++t) {
        // async-gather the 16 precomputed xw rows (16 x 3KB) into smem
        {
            const float* src_row = g_P + (size_t)sh_row[my_g * 64 + t] * TH;
            #pragma unroll
            for (int i = 0; i < 12; ++i) {
                int c16 = my_c16 + 16 * i;
                cp_async16(xw_dst_base + c16 * 16, src_row + c16 * 4);
            }
            asm volatile("cp.async.commit_group;");
        }

        unsigned long long accR[8], accZ[8], ghN[8];
        #pragma unroll
        for (int g = 0; g < 8; ++g) { accR[g] = bR2; accZ[g] = bZ2; ghN[g] = bN2; }

        const float* wph = g_WhhT2 + j;
        #pragma unroll 4
        for (int k = 0; k < Hh; ++k) {
            float wr = wph[k * TH], wz = wph[k * TH + Hh], wn = wph[k * TH + 2 * Hh];
            unsigned long long wr2 = pack2(wr, wr), wz2 = pack2(wz, wz), wn2 = pack2(wn, wn);
            const ulonglong2* hrow = reinterpret_cast<const ulonglong2*>(&sh_h[k][0]);
            #pragma unroll
            for (int q = 0; q < 4; ++q) {
                ulonglong2 hp = hrow[q];        // pairs 2q, 2q+1
                ffma2(accR[2 * q], wr2, hp.x);
                ffma2(accZ[2 * q], wz2, hp.x);
                ffma2(ghN[2 * q],  wn2, hp.x);
                ffma2(accR[2 * q + 1], wr2, hp.y);
                ffma2(accZ[2 * q + 1], wz2, hp.y);
                ffma2(ghN[2 * q + 1],  wn2, hp.y);
            }
        }

        asm volatile("cp.async.wait_group 0;" ::: "memory");
        __syncthreads();

        float hnew[16];
        #pragma unroll
        for (int gg = 0; gg < 8; ++gg) {
            const float* x0 = sh_xw + (2 * gg) * TH + j;
            const float* x1 = sh_xw + (2 * gg + 1) * TH + j;
            float2 aR = unpack2(accR[gg]);
            float2 aZ = unpack2(accZ[gg]);
            float2 hN = unpack2(ghN[gg]);
            float r0 = sig_fast(aR.x + x0[0]);
            float z0 = sig_fast(aZ.x + x0[Hh]);
            float n0 = tanh_fast(x0[2 * Hh] + r0 * hN.x);
            hnew[2 * gg]     = (1.0f - z0) * n0 + z0 * sh_h[j][2 * gg];
            float r1 = sig_fast(aR.y + x1[0]);
            float z1 = sig_fast(aZ.y + x1[Hh]);
            float n1 = tanh_fast(x1[2 * Hh] + r1 * hN.y);
            hnew[2 * gg + 1] = (1.0f - z1) * n1 + z1 * sh_h[j][2 * gg + 1];
        }
        __syncthreads();
        #pragma unroll
        for (int g = 0; g < 16; ++g) sh_h[j][g] = hnew[g];
        __syncthreads();
    }

    const int off = (dir == 0) ? (C1d + 6 * Cc) : (C1d + 6 * Cc + Hh);  // 400 / 656
    #pragma unroll
    for (int g = 0; g < 16; ++g)
        g_F[(size_t)(seq0 + g) * FD + off + j] = sh_h[j][g];
}

// ---------------- 1D GRU: 32 blocks (one per batch) x 256 threads ----------------
__global__ void gru1d_kernel(const float* __restrict__ bhh) {
    const int b = blockIdx.x;
    const int j = threadIdx.x;
    __shared__ float sh[Hh];
    sh[j] = 0.0f;
    const float br = bhh[j], bz = bhh[Hh + j], bn = bhh[2 * Hh + j];
    __syncthreads();

    for (int t = 0; t < 64; ++t) {
        float aR = br, aZ = bz, aN = bn;
        const float* wp = g_Whh1T + j;
        #pragma unroll 8
        for (int k = 0; k < Hh; ++k) {
            float hv = sh[k];
            aR = fmaf(wp[k * TH],          hv, aR);
            aZ = fmaf(wp[k * TH + Hh],     hv, aZ);
            aN = fmaf(wp[k * TH + 2 * Hh], hv, aN);
        }
        const float* xw = g_XW1 + (size_t)(b * 64 + t) * TH;  // includes bih
        float r = sig_fast(xw[j] + aR);
        float z = sig_fast(xw[Hh + j] + aZ);
        float n = tanh_fast(xw[2 * Hh + j] + r * aN);
        float hnew = (1.0f - z) * n + z * sh[j];
        __syncthreads();
        sh[j] = hnew;
        __syncthreads();
    }
    g_G[(size_t)b * GD + 3 * FD + j] = sh[j];
}

// ---------------- g = [f.max(1), f.mean(1), f.min(1)] -> G[:, 0:2736] ----------------
__global__ void finalg_kernel() {
    const int b = blockIdx.x;
    for (int c = threadIdx.x; c < FD; c += 256) {
        float mx = -FLT_MAX, mn = FLT_MAX, sm = 0.0f;
        for (int n = 0; n < Nn; ++n) {
            float v = g_F[(size_t)(b * Nn + n) * FD + c];
            mx = fmaxf(mx, v); mn = fminf(mn, v); sm += v;
        }
        g_G[(size_t)b * GD + c]          = mx;
        g_G[(size_t)b * GD + FD + c]     = sm * (1.0f / 64.0f);
        g_G[(size_t)b * GD + 2 * FD + c] = mn;
    }
}

// ---------------- fc1 (relu) ----------------
__global__ void fc1_kernel(const float* __restrict__ fc1_b) {
    const int b = blockIdx.x;
    const int o = threadIdx.x;
    __shared__ float sg[GD];
    for (int k = o; k < GD; k += 256) sg[k] = g_G[(size_t)b * GD + k];
    __syncthreads();
    float acc = fc1_b[o];
    #pragma unroll 4
    for (int k = 0; k < GD; ++k) acc = fmaf(sg[k], g_fc1Wt[(size_t)k * Hh + o], acc);
    g_H2[b * Hh + o] = fmaxf(acc, 0.0f);
}

// ---------------- fc2 ----------------
__global__ void fc2_kernel(const float* __restrict__ fc2_W, const float* __restrict__ fc2_b,
                           float* __restrict__ out) {
    const int b = blockIdx.x;
    const int j = threadIdx.x;
    __shared__ float red[256];
    red[j] = g_H2[b * Hh + j] * fc2_W[j];
    __syncthreads();
    for (int s = 128; s > 0; s >>= 1) {
        if (j < s) red[j] += red[j + s];
        __syncthreads();
    }
    if (j == 0) out[b] = red[0] + fc2_b[0];
}

// ---------------- launch ----------------
extern "C" void kernel_launch(void* const* d_in, const int* in_sizes, int n_in,
                              void* d_out, int out_size) {
    const float* x1     = (const float*)d_in[0];
    const float* states = (const float*)d_in[1];
    const int*   perm1r = (const int*)d_in[2];
    const int*   perm2r = (const int*)d_in[3];
    const float* g2Wih  = (const float*)d_in[4];
    const float* g2Whh  = (const float*)d_in[5];
    const float* g2bih  = (const float*)d_in[6];
    const float* g2bhh  = (const float*)d_in[7];
    const float* g1Wih  = (const float*)d_in[8];
    const float* g1Whh  = (const float*)d_in[9];
    const float* g1bih  = (const float*)d_in[10];
    const float* g1bhh  = (const float*)d_in[11];
    const float* fc1W   = (const float*)d_in[12];
    const float* fc1b   = (const float*)d_in[13];
    const float* fc2W   = (const float*)d_in[14];
    const float* fc2b   = (const float*)d_in[15];
    float* out = (float*)d_out;

    float *whhT2, *whh1T, *fc1Wt, *xw1, *Fbuf, *Pbuf;
    cudaGetSymbolAddress((void**)&whhT2, g_WhhT2);
    cudaGetSymbolAddress((void**)&whh1T, g_Whh1T);
    cudaGetSymbolAddress((void**)&fc1Wt, g_fc1Wt);
    cudaGetSymbolAddress((void**)&xw1,   g_XW1);
    cudaGetSymbolAddress((void**)&Fbuf,  g_F);
    cudaGetSymbolAddress((void**)&Pbuf,  g_P);

    const int GRU2D_SMEM = (256 * 20 + 16 * TH + 16 * 64) * 4;   // 73728
    cudaFuncSetAttribute(gru2d_kernel, cudaFuncAttributeMaxDynamicSharedMemorySize, GRU2D_SMEM);

    // 1
    transpose_kernel<<<(TH * Hh + 255) / 256, 256>>>(g2Whh, whhT2, TH, Hh);
    // 2: P = states @ g2Wih^T + g2bih   (M=131072, N=768, K=64)
    {
        dim3 g(TH / 64, (Bb * Nn * Mm) / 128);
        gemm128_kernel<<<g, dim3(16, 16)>>>(states, g2Wih, g2bih, Pbuf, Cc, TH);
    }
    // 3
    conv_perm2_kernel<<<2, 256>>>(perm1r, perm2r);
    // 4 — target of ncu -s 5 -c 1 (2 harness launches precede ours)
    {
        dim3 ggrid(128, 2);
        gru2d_kernel<<<ggrid, 256, GRU2D_SMEM>>>(g2bhh);
    }
    // 5
    stats_kernel<<<Bb * Nn, 64>>>(states, x1);
    // 6
    transpose_kernel<<<(TH * Hh + 255) / 256, 256>>>(g1Whh, whh1T, TH, Hh);
    // 7: XW1 = F @ g1Wih^T + g1bih   (M=2048, N=768, K=912)
    {
        dim3 g(TH / 64, (Bb * Nn) / 128);
        gemm128_kernel<<<g, dim3(16, 16)>>>(Fbuf, g1Wih, g1bih, xw1, FD, TH);
    }
    // 8
    gru1d_kernel<<<Bb, Hh>>>(g1bhh);
    // 9
    finalg_kernel<<<Bb, 256>>>();
    // 10
    transpose_kernel<<<(Hh * GD + 255) / 256, 256>>>(fc1W, fc1Wt, Hh, GD);
    // 11
    fc1_kernel<<<Bb, Hh>>>(fc1b);
    // 12
    fc2_kernel<<<Bb, 256>>>(fc2W, fc2b, out);
}

// round 9
// speedup vs baseline: 1.6455x; 1.0050x over previous
#include <cuda_runtime.h>
#include <cstdint>
#include <cfloat>
#include <math.h>

#define Bb 32
#define Nn 64
#define Mm 64
#define Cc 64
#define C1d 16
#define Hh 256
#define TH 768
#define FD 912
#define GD 2992

// ---------------- device scratch ----------------
__device__ float g_P[(size_t)Bb * Nn * Mm * TH];   // input proj of every states row [131072][768]
__device__ float g_F[(size_t)Bb * Nn * FD];        // f [2048][912]
__device__ float g_XW1[(size_t)Bb * Nn * TH];      // gru1d input proj [2048][768]
__device__ float g_WhhT2[Hh * TH];                 // [256][768]
__device__ float g_Whh1T[Hh * TH];                 // [256][768]
__device__ float g_fc1Wt[GD * Hh];                 // [2992][256]
__device__ float g_G[Bb * GD];
__device__ float g_H2[Bb * Hh];
__device__ int   g_perm1[Nn * Mm];
__device__ int   g_perm2[Nn * Nn];

// ---------------- helpers ----------------
__device__ __forceinline__ unsigned long long pack2(float lo, float hi) {
    unsigned long long r;
    asm("mov.b64 %0, {%1, %2};" : "=l"(r) : "f"(lo), "f"(hi));
    return r;
}
__device__ __forceinline__ float2 unpack2(unsigned long long v) {
    float2 r;
    asm("mov.b64 {%0, %1}, %2;" : "=f"(r.x), "=f"(r.y) : "l"(v));
    return r;
}
__device__ __forceinline__ void ffma2(unsigned long long& d, unsigned long long a, unsigned long long b) {
    asm("fma.rn.f32x2 %0, %1, %2, %0;" : "+l"(d) : "l"(a), "l"(b));
}
__device__ __forceinline__ float tanh_fast(float x) {
    float y; asm("tanh.approx.f32 %0, %1;" : "=f"(y) : "f"(x)); return y;
}
__device__ __forceinline__ float sig_fast(float x) {
    return fmaf(tanh_fast(x * 0.5f), 0.5f, 0.5f);
}
__device__ __forceinline__ void cp_async16(uint32_t dst, const void* src) {
    asm volatile("cp.async.cg.shared.global [%0], [%1], 16;" :: "r"(dst), "l"(src));
}

// ---------------- both perm conversions in one kernel (int64 vs int32 detect) ----------------
__global__ void conv_perm2_kernel(const int* __restrict__ r1, const int* __restrict__ r2) {
    const int* raw = blockIdx.x ? r2 : r1;
    int* out = blockIdx.x ? g_perm2 : g_perm1;
    const int n = Nn * Mm;   // 4096 both
    __shared__ int notI64;
    if (threadIdx.x == 0) notI64 = 0;
    __syncthreads();
    for (int i = threadIdx.x; i < n / 2; i += blockDim.x)
        if (raw[2 * i + 1] != 0) notI64 = 1;
    __syncthreads();
    if (notI64) { for (int i = threadIdx.x; i < n; i += blockDim.x) out[i] = raw[i]; }
    else        { for (int i = threadIdx.x; i < n; i += blockDim.x) out[i] = raw[2 * i]; }
}

// ---------------- transpose in[R][C] -> out[C][R] ----------------
__global__ void transpose_kernel(const float* __restrict__ in, float* __restrict__ out, int R, int C) {
    int idx = blockIdx.x * 256 + threadIdx.x;
    if (idx < R * C) { int r = idx / C, c = idx % C; out[c * R + r] = in[idx]; }
}

// ---------------- stats over states + x1 copy -> F[:, 0:400] ----------------
__global__ void stats_kernel(const float* __restrict__ states, const float* __restrict__ x1) {
    int bi = blockIdx.x;               // b*64 + i
    int b = bi >> 6, i = bi & 63;
    int c = threadIdx.x;               // 64 threads
    float* fr = g_F + (size_t)bi * FD;

    float mx = -FLT_MAX, mn = FLT_MAX, sm = 0.0f;
    for (int n = 0; n < Nn; ++n) {
        float v = states[(((size_t)(b * Nn + n)) * Mm + i) * Cc + c];
        mx = fmaxf(mx, v); mn = fminf(mn, v); sm += v;
    }
    fr[C1d + c]          = mx;
    fr[C1d + Cc + c]     = sm * (1.0f / 64.0f);
    fr[C1d + 2 * Cc + c] = mn;

    mx = -FLT_MAX; mn = FLT_MAX; sm = 0.0f;
    for (int m = 0; m < Mm; ++m) {
        float v = states[(((size_t)(b * Nn + i)) * Mm + m) * Cc + c];
        mx = fmaxf(mx, v); mn = fminf(mn, v); sm += v;
    }
    fr[C1d + 3 * Cc + c] = mx;
    fr[C1d + 4 * Cc + c] = sm * (1.0f / 64.0f);
    fr[C1d + 5 * Cc + c] = mn;

    if (c < C1d) fr[c] = x1[bi * C1d + c];
}

// ---------------- SGEMM 128x64 tile: C[M][N] = A[M][K] @ B[N][K]^T + bias[N] ----------------
__global__ void gemm128_kernel(const float* __restrict__ A, const float* __restrict__ Bm,
                               const float* __restrict__ bias, float* __restrict__ Cm,
                               int K, int Ndim) {
    __shared__ __align__(16) float As[16][132];
    __shared__ __align__(16) float Bs[16][68];
    const int tx = threadIdx.x, ty = threadIdx.y;
    const int tid = ty * 16 + tx;
    const int m0 = blockIdx.y * 128, n0 = blockIdx.x * 64;

    float acc[8][4];
    #pragma unroll
    for (int i = 0; i < 8; ++i)
        #pragma unroll
        for (int jj = 0; jj < 4; ++jj) acc[i][jj] = 0.0f;

    for (int k0 = 0; k0 < K; k0 += 16) {
        #pragma unroll
        for (int e = 0; e < 8; ++e) {
            int idx = tid + e * 256;
            int r = idx >> 4, kk = idx & 15;
            As[kk][r] = A[(size_t)(m0 + r) * K + k0 + kk];
        }
        #pragma unroll
        for (int e = 0; e < 4; ++e) {
            int idx = tid + e * 256;
            int r = idx >> 4, kk = idx & 15;
            Bs[kk][r] = Bm[(size_t)(n0 + r) * K + k0 + kk];
        }
        __syncthreads();
        #pragma unroll
        for (int kk = 0; kk < 16; ++kk) {
            float4 a0 = *reinterpret_cast<const float4*>(&As[kk][ty * 8]);
            float4 a1 = *reinterpret_cast<const float4*>(&As[kk][ty * 8 + 4]);
            float4 b4 = *reinterpret_cast<const float4*>(&Bs[kk][tx * 4]);
            float av[8] = {a0.x, a0.y, a0.z, a0.w, a1.x, a1.y, a1.z, a1.w};
            float bv[4] = {b4.x, b4.y, b4.z, b4.w};
            #pragma unroll
            for (int i = 0; i < 8; ++i)
                #pragma unroll
                for (int jj = 0; jj < 4; ++jj)
                    acc[i][jj] = fmaf(av[i], bv[jj], acc[i][jj]);
        }
        __syncthreads();
    }
    float4 bia = *reinterpret_cast<const float4*>(&bias[n0 + tx * 4]);
    #pragma unroll
    for (int i = 0; i < 8; ++i) {
        float4 v = make_float4(acc[i][0] + bia.x, acc[i][1] + bia.y,
                               acc[i][2] + bia.z, acc[i][3] + bia.w);
        *reinterpret_cast<float4*>(&Cm[(size_t)(m0 + ty * 8 + i) * Ndim + n0 + tx * 4]) = v;
    }
}

// ---------------- persistent 2D GRU: G=32 seqs/CTA, 1 CTA/SM, 128 CTAs ----------------
// smem: h[256][36] + xw[32][768] + rows[32][64] = 143360 B
__global__ void __launch_bounds__(256, 1)
gru2d_kernel(const float* __restrict__ bhh) {
    const int dir  = blockIdx.x >> 6;           // 0: sd1, 1: sd2
    const int seq0 = (blockIdx.x & 63) * 32;    // seq within dir, 0..2047
    const int j    = threadIdx.x;

    extern __shared__ __align__(16) float dyn[];
    float (*sh_h)[36] = (float (*)[36])dyn;              // [256][36]
    float* sh_xw  = dyn + 256 * 36;                      // [32][768]
    int*   sh_row = (int*)(dyn + 256 * 36 + 32 * TH);    // [32][64]

    #pragma unroll
    for (int g = 0; g < 36; ++g) sh_h[j][g] = 0.0f;

    // precompute all gather row indices
    for (int e = j; e < 32 * 64; e += 256) {
        int g = e >> 6, t = e & 63;
        int s = seq0 + g;                      // 0..2047
        int b = s >> 6, n = s & 63;
        sh_row[e] = (dir == 0)
            ? (b * Nn + n) * Mm + g_perm1[n * Mm + t]
            : (b * Nn + g_perm2[n * Nn + t]) * Mm + n;
    }

    const float bhhr = bhh[j], bhhz = bhh[Hh + j], bhhn = bhh[2 * Hh + j];
    const unsigned long long bR2 = pack2(bhhr, bhhr);
    const unsigned long long bZ2 = pack2(bhhz, bhhz);
    const unsigned long long bN2 = pack2(bhhn, bhhn);

    const int my_g  = j >> 3;                  // 32 rows, 8 threads per row
    const int my_c  = j & 7;
    uint32_t xw_dst_base = (uint32_t)__cvta_generic_to_shared(sh_xw + my_g * TH);
    __syncthreads();

    for (int t = 0; t < 64; ++t) {
        // async-gather the 32 precomputed xw rows (32 x 3KB) into smem
        {
            const float* src_row = g_P + (size_t)sh_row[my_g * 64 + t] * TH;
            #pragma unroll
            for (int i = 0; i < 24; ++i) {
                int c16 = my_c + 8 * i;        // 0..191 (16B chunks)
                cp_async16(xw_dst_base + c16 * 16, src_row + c16 * 4);
            }
            asm volatile("cp.async.commit_group;");
        }

        // ----- recurrent matvec for 16 lane-pairs (32 seqs) -----
        unsigned long long accR[16], accZ[16], ghN[16];
        #pragma unroll
        for (int g = 0; g < 16; ++g) { accR[g] = bR2; accZ[g] = bZ2; ghN[g] = bN2; }

        const float* wph = g_WhhT2 + j;
        #pragma unroll 4
        for (int k = 0; k < Hh; ++k) {
            float wr = wph[k * TH], wz = wph[k * TH + Hh], wn = wph[k * TH + 2 * Hh];
            unsigned long long wr2 = pack2(wr, wr), wz2 = pack2(wz, wz), wn2 = pack2(wn, wn);
            const ulonglong2* hrow = reinterpret_cast<const ulonglong2*>(&sh_h[k][0]);
            #pragma unroll
            for (int q = 0; q < 8; ++q) {
                ulonglong2 hp = hrow[q];       // pairs 2q, 2q+1
                ffma2(accR[2 * q],     wr2, hp.x);
                ffma2(accZ[2 * q],     wz2, hp.x);
                ffma2(ghN[2 * q],      wn2, hp.x);
                ffma2(accR[2 * q + 1], wr2, hp.y);
                ffma2(accZ[2 * q + 1], wz2, hp.y);
                ffma2(ghN[2 * q + 1],  wn2, hp.y);
            }
        }

        asm volatile("cp.async.wait_group 0;" ::: "memory");
        __syncthreads();

        float hnew[32];
        #pragma unroll
        for (int gg = 0; gg < 16; ++gg) {
            const float* x0 = sh_xw + (2 * gg) * TH + j;
            const float* x1 = sh_xw + (2 * gg + 1) * TH + j;
            float2 aR = unpack2(accR[gg]);
            float2 aZ = unpack2(accZ[gg]);
            float2 hN = unpack2(ghN[gg]);
            float r0 = sig_fast(aR.x + x0[0]);
            float z0 = sig_fast(aZ.x + x0[Hh]);
            float n0 = tanh_fast(x0[2 * Hh] + r0 * hN.x);
            hnew[2 * gg]     = (1.0f - z0) * n0 + z0 * sh_h[j][2 * gg];
            float r1 = sig_fast(aR.y + x1[0]);
            float z1 = sig_fast(aZ.y + x1[Hh]);
            float n1 = tanh_fast(x1[2 * Hh] + r1 * hN.y);
            hnew[2 * gg + 1] = (1.0f - z1) * n1 + z1 * sh_h[j][2 * gg + 1];
        }
        __syncthreads();
        #pragma unroll
        for (int g = 0; g < 32; ++g) sh_h[j][g] = hnew[g];
        __syncthreads();
    }

    const int off = (dir == 0) ? (C1d + 6 * Cc) : (C1d + 6 * Cc + Hh);  // 400 / 656
    #pragma unroll
    for (int g = 0; g < 32; ++g)
        g_F[(size_t)(seq0 + g) * FD + off + j] = sh_h[j][g];
}

// ---------------- 1D GRU: 32 blocks (one per batch) x 256 threads ----------------
__global__ void gru1d_kernel(const float* __restrict__ bhh) {
    const int b = blockIdx.x;
    const int j = threadIdx.x;
    __shared__ float sh[Hh];
    sh[j] = 0.0f;
    const float br = bhh[j], bz = bhh[Hh + j], bn = bhh[2 * Hh + j];
    __syncthreads();

    for (int t = 0; t < 64; ++t) {
        float aR = br, aZ = bz, aN = bn;
        const float* wp = g_Whh1T + j;
        #pragma unroll 8
        for (int k = 0; k < Hh; ++k) {
            float hv = sh[k];
            aR = fmaf(wp[k * TH],          hv, aR);
            aZ = fmaf(wp[k * TH + Hh],     hv, aZ);
            aN = fmaf(wp[k * TH + 2 * Hh], hv, aN);
        }
        const float* xw = g_XW1 + (size_t)(b * 64 + t) * TH;  // includes bih
        float r = sig_fast(xw[j] + aR);
        float z = sig_fast(xw[Hh + j] + aZ);
        float n = tanh_fast(xw[2 * Hh + j] + r * aN);
        float hnew = (1.0f - z) * n + z * sh[j];
        __syncthreads();
        sh[j] = hnew;
        __syncthreads();
    }
    g_G[(size_t)b * GD + 3 * FD + j] = sh[j];
}

// ---------------- g = [f.max(1), f.mean(1), f.min(1)] -> G[:, 0:2736] ----------------
__global__ void finalg_kernel() {
    const int b = blockIdx.x;
    for (int c = threadIdx.x; c < FD; c += 256) {
        float mx = -FLT_MAX, mn = FLT_MAX, sm = 0.0f;
        for (int n = 0; n < Nn; ++n) {
            float v = g_F[(size_t)(b * Nn + n) * FD + c];
            mx = fmaxf(mx, v); mn = fminf(mn, v); sm += v;
        }
        g_G[(size_t)b * GD + c]          = mx;
        g_G[(size_t)b * GD + FD + c]     = sm * (1.0f / 64.0f);
        g_G[(size_t)b * GD + 2 * FD + c] = mn;
    }
}

// ---------------- fc1 (relu) ----------------
__global__ void fc1_kernel(const float* __restrict__ fc1_b) {
    const int b = blockIdx.x;
    const int o = threadIdx.x;
    __shared__ float sg[GD];
    for (int k = o; k < GD; k += 256) sg[k] = g_G[(size_t)b * GD + k];
    __syncthreads();
    float acc = fc1_b[o];
    #pragma unroll 4
    for (int k = 0; k < GD; ++k) acc = fmaf(sg[k], g_fc1Wt[(size_t)k * Hh + o], acc);
    g_H2[b * Hh + o] = fmaxf(acc, 0.0f);
}

// ---------------- fc2 ----------------
__global__ void fc2_kernel(const float* __restrict__ fc2_W, const float* __restrict__ fc2_b,
                           float* __restrict__ out) {
    const int b = blockIdx.x;
    const int j = threadIdx.x;
    __shared__ float red[256];
    red[j] = g_H2[b * Hh + j] * fc2_W[j];
    __syncthreads();
    for (int s = 128; s > 0; s >>= 1) {
        if (j < s) red[j] += red[j + s];
        __syncthreads();
    }
    if (j == 0) out[b] = red[0] + fc2_b[0];
}

// ---------------- launch ----------------
extern "C" void kernel_launch(void* const* d_in, const int* in_sizes, int n_in,
                              void* d_out, int out_size) {
    const float* x1     = (const float*)d_in[0];
    const float* states = (const float*)d_in[1];
    const int*   perm1r = (const int*)d_in[2];
    const int*   perm2r = (const int*)d_in[3];
    const float* g2Wih  = (const float*)d_in[4];
    const float* g2Whh  = (const float*)d_in[5];
    const float* g2bih  = (const float*)d_in[6];
    const float* g2bhh  = (const float*)d_in[7];
    const float* g1Wih  = (const float*)d_in[8];
    const float* g1Whh  = (const float*)d_in[9];
    const float* g1bih  = (const float*)d_in[10];
    const float* g1bhh  = (const float*)d_in[11];
    const float* fc1W   = (const float*)d_in[12];
    const float* fc1b   = (const float*)d_in[13];
    const float* fc2W   = (const float*)d_in[14];
    const float* fc2b   = (const float*)d_in[15];
    float* out = (float*)d_out;

    float *whhT2, *whh1T, *fc1Wt, *xw1, *Fbuf, *Pbuf;
    cudaGetSymbolAddress((void**)&whhT2, g_WhhT2);
    cudaGetSymbolAddress((void**)&whh1T, g_Whh1T);
    cudaGetSymbolAddress((void**)&fc1Wt, g_fc1Wt);
    cudaGetSymbolAddress((void**)&xw1,   g_XW1);
    cudaGetSymbolAddress((void**)&Fbuf,  g_F);
    cudaGetSymbolAddress((void**)&Pbuf,  g_P);

    const int GRU2D_SMEM = (256 * 36 + 32 * TH + 32 * 64) * 4;   // 143360
    cudaFuncSetAttribute(gru2d_kernel, cudaFuncAttributeMaxDynamicSharedMemorySize, GRU2D_SMEM);

    // 1
    transpose_kernel<<<(TH * Hh + 255) / 256, 256>>>(g2Whh, whhT2, TH, Hh);
    // 2: P = states @ g2Wih^T + g2bih   (M=131072, N=768, K=64)
    {
        dim3 g(TH / 64, (Bb * Nn * Mm) / 128);
        gemm128_kernel<<<g, dim3(16, 16)>>>(states, g2Wih, g2bih, Pbuf, Cc, TH);
    }
    // 3
    conv_perm2_kernel<<<2, 256>>>(perm1r, perm2r);
    // 4 — ncu target (-s 5 -c 1; 2 harness launches precede ours)
    gru2d_kernel<<<128, 256, GRU2D_SMEM>>>(g2bhh);
    // 5
    stats_kernel<<<Bb * Nn, 64>>>(states, x1);
    // 6
    transpose_kernel<<<(TH * Hh + 255) / 256, 256>>>(g1Whh, whh1T, TH, Hh);
    // 7: XW1 = F @ g1Wih^T + g1bih   (M=2048, N=768, K=912)
    {
        dim3 g(TH / 64, (Bb * Nn) / 128);
        gemm128_kernel<<<g, dim3(16, 16)>>>(Fbuf, g1Wih, g1bih, xw1, FD, TH);
    }
    // 8
    gru1d_kernel<<<Bb, Hh>>>(g1bhh);
    // 9
    finalg_kernel<<<Bb, 256>>>();
    // 10
    transpose_kernel<<<(Hh * GD + 255) / 256, 256>>>(fc1W, fc1Wt, Hh, GD);
    // 11
    fc1_kernel<<<Bb, Hh>>>(fc1b);
    // 12
    fc2_kernel<<<Bb, 256>>>(fc2W, fc2b, out);
}